// round 4
// baseline (speedup 1.0000x reference)
#include <cuda_runtime.h>
#include <math.h>

// Problem constants
#define B_    8
#define N_    1024
#define DIM_  768
#define CR_   384
#define HEADS_ 12
#define HD_   32
#define ROWS_ (B_ * N_)   // 8192

// Scratch (device globals; no allocations allowed)
__device__ float g_xn[ROWS_ * DIM_];  // LN0(x)
__device__ float g_h [ROWS_ * CR_];   // proj output
__device__ float g_y [ROWS_ * CR_];   // LN1(h)
__device__ float g_q [ROWS_ * CR_];
__device__ float g_k [ROWS_ * CR_];
__device__ float g_v [ROWS_ * CR_];

// ---------------------------------------------------------------------------
// Row-wise LayerNorm: one block per row, 256 threads.
// ---------------------------------------------------------------------------
__global__ __launch_bounds__(256) void ln_kernel(
    const float* __restrict__ in, const float* __restrict__ gamma,
    const float* __restrict__ beta, float* __restrict__ out, int C)
{
    const int row = blockIdx.x;
    const float* p = in + (size_t)row * C;
    float sum = 0.f, sq = 0.f;
    for (int i = threadIdx.x; i < C; i += 256) {
        float v = p[i];
        sum += v;
        sq  += v * v;
    }
    __shared__ float s1[8], s2[8];
    #pragma unroll
    for (int o = 16; o; o >>= 1) {
        sum += __shfl_xor_sync(0xffffffffu, sum, o);
        sq  += __shfl_xor_sync(0xffffffffu, sq,  o);
    }
    const int w = threadIdx.x >> 5, l = threadIdx.x & 31;
    if (l == 0) { s1[w] = sum; s2[w] = sq; }
    __syncthreads();
    if (w == 0) {
        sum = (l < 8) ? s1[l] : 0.f;
        sq  = (l < 8) ? s2[l] : 0.f;
        #pragma unroll
        for (int o = 4; o; o >>= 1) {
            sum += __shfl_xor_sync(0xffffffffu, sum, o);
            sq  += __shfl_xor_sync(0xffffffffu, sq,  o);
        }
        if (l == 0) { s1[0] = sum; s2[0] = sq; }
    }
    __syncthreads();
    const float invC = 1.0f / (float)C;
    const float mean = s1[0] * invC;
    const float var  = s2[0] * invC - mean * mean;
    const float rstd = rsqrtf(var + 1e-5f);
    float* q = out + (size_t)row * C;
    for (int i = threadIdx.x; i < C; i += 256) {
        float v = p[i];
        q[i] = (v - mean) * rstd * gamma[i] + beta[i];
    }
}

// ---------------------------------------------------------------------------
// GEMM (NT): C[M,N] = A[M,K] * B[N,K]^T (+ bias[N])
// Tiles: BM=128, BN=64, BK=16. 256 threads, 8x4 micro-tile per thread.
// Requires M%128==0, N%64==0, K%16==0 (holds: 8192, 384, {768,384}).
// ---------------------------------------------------------------------------
__global__ __launch_bounds__(256) void gemm_nt_kernel(
    const float* __restrict__ A, const float* __restrict__ Bm,
    const float* __restrict__ bias, float* __restrict__ C,
    int M, int N, int K)
{
    __shared__ __align__(16) float As[16][128];
    __shared__ __align__(16) float Bs[16][64];

    const int tid = threadIdx.x;
    const int tx  = tid & 15;       // 0..15 -> 4 cols each
    const int ty  = tid >> 4;       // 0..15 -> 8 rows each
    const int rowBase = blockIdx.y * 128;
    const int colBase = blockIdx.x * 64;

    float acc[8][4];
    #pragma unroll
    for (int i = 0; i < 8; i++)
        #pragma unroll
        for (int j = 0; j < 4; j++) acc[i][j] = 0.f;

    const int lrow = tid >> 2;   // 0..63
    const int lcv  = tid & 3;    // float4 slot within 16-wide K

    for (int k0 = 0; k0 < K; k0 += 16) {
        #pragma unroll
        for (int l = 0; l < 2; l++) {
            int row = lrow + l * 64;
            float4 v = *reinterpret_cast<const float4*>(
                A + (size_t)(rowBase + row) * K + k0 + lcv * 4);
            As[lcv * 4 + 0][row] = v.x;
            As[lcv * 4 + 1][row] = v.y;
            As[lcv * 4 + 2][row] = v.z;
            As[lcv * 4 + 3][row] = v.w;
        }
        {
            float4 v = *reinterpret_cast<const float4*>(
                Bm + (size_t)(colBase + lrow) * K + k0 + lcv * 4);
            Bs[lcv * 4 + 0][lrow] = v.x;
            Bs[lcv * 4 + 1][lrow] = v.y;
            Bs[lcv * 4 + 2][lrow] = v.z;
            Bs[lcv * 4 + 3][lrow] = v.w;
        }
        __syncthreads();
        #pragma unroll
        for (int kk = 0; kk < 16; kk++) {
            float a[8], bb[4];
            #pragma unroll
            for (int i = 0; i < 8; i++) a[i] = As[kk][ty * 8 + i];
            #pragma unroll
            for (int j = 0; j < 4; j++) bb[j] = Bs[kk][tx * 4 + j];
            #pragma unroll
            for (int i = 0; i < 8; i++)
                #pragma unroll
                for (int j = 0; j < 4; j++)
                    acc[i][j] = fmaf(a[i], bb[j], acc[i][j]);
        }
        __syncthreads();
    }

    float4 bv = make_float4(0.f, 0.f, 0.f, 0.f);
    if (bias) bv = *reinterpret_cast<const float4*>(bias + colBase + tx * 4);
    #pragma unroll
    for (int i = 0; i < 8; i++) {
        float4 o;
        o.x = acc[i][0] + bv.x;
        o.y = acc[i][1] + bv.y;
        o.z = acc[i][2] + bv.z;
        o.w = acc[i][3] + bv.w;
        *reinterpret_cast<float4*>(
            C + (size_t)(rowBase + ty * 8 + i) * N + colBase + tx * 4) = o;
    }
}

// ---------------------------------------------------------------------------
// Flash attention per (b,h): grid = (N/64, B*HEADS), 256 threads.
// Q/K/V stored [B*N, CR] with head h at column h*32.
// Block handles 64 query rows; streams K/V in 64-row tiles; online softmax.
// Epilogue fuses residual: out = h + attn.
// ---------------------------------------------------------------------------
__global__ __launch_bounds__(256) void attn_kernel(
    const float* __restrict__ Q, const float* __restrict__ K,
    const float* __restrict__ V, const float* __restrict__ H,
    float* __restrict__ Out)
{
    __shared__ __align__(16) float ks[64][32];
    __shared__ __align__(16) float vs[64][32];
    __shared__ float ss[64][65];
    __shared__ float m_s[64], l_s[64], a_s[64];

    const int tid = threadIdx.x;
    const int r = tid & 63;       // query row within tile
    const int g = tid >> 6;       // 0..3: 16-col score group / 8-dim pv group
    const int bh = blockIdx.y;
    const int b  = bh / HEADS_;
    const int h  = bh % HEADS_;
    const int n0 = blockIdx.x * 64;
    const size_t headoff = (size_t)(b * N_) * CR_ + h * HD_;
    const float scale = 0.17677669529663687f;  // 1/sqrt(32)

    // q row -> registers (4x redundant across g groups, once per block)
    float qreg[32];
    {
        const float4* qp = reinterpret_cast<const float4*>(
            Q + headoff + (size_t)(n0 + r) * CR_);
        #pragma unroll
        for (int d4 = 0; d4 < 8; d4++) {
            float4 v = qp[d4];
            qreg[d4 * 4 + 0] = v.x;
            qreg[d4 * 4 + 1] = v.y;
            qreg[d4 * 4 + 2] = v.z;
            qreg[d4 * 4 + 3] = v.w;
        }
    }

    if (tid < 64) { m_s[tid] = -INFINITY; l_s[tid] = 0.f; }
    float o[8];
    #pragma unroll
    for (int i = 0; i < 8; i++) o[i] = 0.f;

    for (int kt = 0; kt < N_ / 64; kt++) {
        __syncthreads();  // previous tile's ss/vs reads done
        const int k0 = kt * 64;
        for (int e = tid; e < 64 * 32; e += 256) {
            int rr = e >> 5, d = e & 31;
            size_t off = headoff + (size_t)(k0 + rr) * CR_ + d;
            ks[rr][d] = K[off];
            vs[rr][d] = V[off];
        }
        __syncthreads();

        // scores: this thread computes s[r][g*16 .. g*16+15]
        #pragma unroll 4
        for (int jj = 0; jj < 16; jj++) {
            const int j = g * 16 + jj;
            const float4* kr = reinterpret_cast<const float4*>(&ks[j][0]);
            float acc = 0.f;
            #pragma unroll
            for (int d4 = 0; d4 < 8; d4++) {
                float4 kv = kr[d4];
                acc = fmaf(qreg[d4 * 4 + 0], kv.x, acc);
                acc = fmaf(qreg[d4 * 4 + 1], kv.y, acc);
                acc = fmaf(qreg[d4 * 4 + 2], kv.z, acc);
                acc = fmaf(qreg[d4 * 4 + 3], kv.w, acc);
            }
            ss[r][j] = acc * scale;
        }
        __syncthreads();

        // online softmax bookkeeping: row owners (tid < 64)
        if (tid < 64) {
            float m_old = m_s[tid];
            float mx = m_old;
            #pragma unroll 8
            for (int j = 0; j < 64; j++) mx = fmaxf(mx, ss[tid][j]);
            float lsum = 0.f;
            #pragma unroll 8
            for (int j = 0; j < 64; j++) {
                float p = __expf(ss[tid][j] - mx);
                ss[tid][j] = p;
                lsum += p;
            }
            float alpha = expf(m_old - mx);  // exact: handles -inf
            m_s[tid] = mx;
            l_s[tid] = l_s[tid] * alpha + lsum;
            a_s[tid] = alpha;
        }
        __syncthreads();

        // o = o*alpha + P @ V  (this thread: dims g*8 .. g*8+7 of row r)
        const float alpha = a_s[r];
        #pragma unroll
        for (int i = 0; i < 8; i++) o[i] *= alpha;
        #pragma unroll 4
        for (int j = 0; j < 64; j++) {
            const float p = ss[r][j];
            const float4* vr = reinterpret_cast<const float4*>(&vs[j][g * 8]);
            float4 v0 = vr[0], v1 = vr[1];
            o[0] = fmaf(p, v0.x, o[0]);
            o[1] = fmaf(p, v0.y, o[1]);
            o[2] = fmaf(p, v0.z, o[2]);
            o[3] = fmaf(p, v0.w, o[3]);
            o[4] = fmaf(p, v1.x, o[4]);
            o[5] = fmaf(p, v1.y, o[5]);
            o[6] = fmaf(p, v1.z, o[6]);
            o[7] = fmaf(p, v1.w, o[7]);
        }
    }

    // epilogue: out = h + attn/l
    const float inv = 1.f / l_s[r];
    const size_t base = (size_t)(b * N_ + n0 + r) * CR_ + h * HD_ + g * 8;
    const float4* hp = reinterpret_cast<const float4*>(H + base);
    float4* op = reinterpret_cast<float4*>(Out + base);
    float4 h0 = hp[0], h1 = hp[1];
    float4 r0, r1;
    r0.x = h0.x + o[0] * inv; r0.y = h0.y + o[1] * inv;
    r0.z = h0.z + o[2] * inv; r0.w = h0.w + o[3] * inv;
    r1.x = h1.x + o[4] * inv; r1.y = h1.y + o[5] * inv;
    r1.z = h1.z + o[6] * inv; r1.w = h1.w + o[7] * inv;
    op[0] = r0; op[1] = r1;
}

// ---------------------------------------------------------------------------
// Launch
// ---------------------------------------------------------------------------
extern "C" void kernel_launch(void* const* d_in, const int* in_sizes, int n_in,
                              void* d_out, int out_size)
{
    (void)in_sizes; (void)n_in; (void)out_size;
    const float* x      = (const float*)d_in[0];
    const float* ln0_g  = (const float*)d_in[1];
    const float* ln0_b  = (const float*)d_in[2];
    const float* w_proj = (const float*)d_in[3];
    const float* b_proj = (const float*)d_in[4];
    const float* ln1_g  = (const float*)d_in[5];
    const float* ln1_b  = (const float*)d_in[6];
    const float* wq     = (const float*)d_in[7];
    const float* wk     = (const float*)d_in[8];
    const float* wv     = (const float*)d_in[9];
    float* out = (float*)d_out;

    float *xn, *h, *y, *q, *k, *v;
    cudaGetSymbolAddress((void**)&xn, g_xn);
    cudaGetSymbolAddress((void**)&h,  g_h);
    cudaGetSymbolAddress((void**)&y,  g_y);
    cudaGetSymbolAddress((void**)&q,  g_q);
    cudaGetSymbolAddress((void**)&k,  g_k);
    cudaGetSymbolAddress((void**)&v,  g_v);

    // 1) xn = LN0(x)
    ln_kernel<<<ROWS_, 256>>>(x, ln0_g, ln0_b, xn, DIM_);

    // 2) h = xn @ w_proj^T + b_proj   [8192, 384]
    gemm_nt_kernel<<<dim3(CR_ / 64, ROWS_ / 128), 256>>>(
        xn, w_proj, b_proj, h, ROWS_, CR_, DIM_);

    // 3) y = LN1(h)
    ln_kernel<<<ROWS_, 256>>>(h, ln1_g, ln1_b, y, CR_);

    // 4) q/k/v = y @ w^T
    gemm_nt_kernel<<<dim3(CR_ / 64, ROWS_ / 128), 256>>>(
        y, wq, nullptr, q, ROWS_, CR_, CR_);
    gemm_nt_kernel<<<dim3(CR_ / 64, ROWS_ / 128), 256>>>(
        y, wk, nullptr, k, ROWS_, CR_, CR_);
    gemm_nt_kernel<<<dim3(CR_ / 64, ROWS_ / 128), 256>>>(
        y, wv, nullptr, v, ROWS_, CR_, CR_);

    // 5) out = h + attention(y)
    attn_kernel<<<dim3(N_ / 64, B_ * HEADS_), 256>>>(q, k, v, h, out);
}

// round 5
// speedup vs baseline: 2.2275x; 2.2275x over previous
#include <cuda_runtime.h>
#include <math.h>
#include <stdint.h>

// Problem constants
#define B_     8
#define N_     1024
#define DIM_   768
#define CR_    384
#define HEADS_ 12
#define HD_    32
#define ROWS_  (B_ * N_)   // 8192

// Scratch (device globals; no allocations allowed)
__device__ float g_xn[ROWS_ * DIM_];  // LN0(x)
__device__ float g_h [ROWS_ * CR_];   // proj output
__device__ float g_y [ROWS_ * CR_];   // LN1(h)
__device__ float g_q [ROWS_ * CR_];
__device__ float g_k [ROWS_ * CR_];
__device__ float g_v [ROWS_ * CR_];

// ---------------------------------------------------------------------------
// tf32 helpers
// ---------------------------------------------------------------------------
__device__ __forceinline__ float to_tf32(float x) {
    uint32_t u;
    asm("cvt.rna.tf32.f32 %0, %1;" : "=r"(u) : "f"(x));
    return __uint_as_float(u);
}

__device__ __forceinline__ void mma_tf32(float* c,
    uint32_t a0, uint32_t a1, uint32_t a2, uint32_t a3,
    uint32_t b0, uint32_t b1)
{
    asm volatile(
        "mma.sync.aligned.m16n8k8.row.col.f32.tf32.tf32.f32 "
        "{%0,%1,%2,%3}, {%4,%5,%6,%7}, {%8,%9}, {%0,%1,%2,%3};"
        : "+f"(c[0]), "+f"(c[1]), "+f"(c[2]), "+f"(c[3])
        : "r"(a0), "r"(a1), "r"(a2), "r"(a3), "r"(b0), "r"(b1));
}

// ---------------------------------------------------------------------------
// Row-wise LayerNorm: one block per row, 256 threads.
// ---------------------------------------------------------------------------
__global__ __launch_bounds__(256) void ln_kernel(
    const float* __restrict__ in, const float* __restrict__ gamma,
    const float* __restrict__ beta, float* __restrict__ out, int C)
{
    const int row = blockIdx.x;
    const float* p = in + (size_t)row * C;
    float sum = 0.f, sq = 0.f;
    for (int i = threadIdx.x; i < C; i += 256) {
        float v = p[i];
        sum += v;
        sq  += v * v;
    }
    __shared__ float s1[8], s2[8];
    #pragma unroll
    for (int o = 16; o; o >>= 1) {
        sum += __shfl_xor_sync(0xffffffffu, sum, o);
        sq  += __shfl_xor_sync(0xffffffffu, sq,  o);
    }
    const int w = threadIdx.x >> 5, l = threadIdx.x & 31;
    if (l == 0) { s1[w] = sum; s2[w] = sq; }
    __syncthreads();
    if (w == 0) {
        sum = (l < 8) ? s1[l] : 0.f;
        sq  = (l < 8) ? s2[l] : 0.f;
        #pragma unroll
        for (int o = 4; o; o >>= 1) {
            sum += __shfl_xor_sync(0xffffffffu, sum, o);
            sq  += __shfl_xor_sync(0xffffffffu, sq,  o);
        }
        if (l == 0) { s1[0] = sum; s2[0] = sq; }
    }
    __syncthreads();
    const float invC = 1.0f / (float)C;
    const float mean = s1[0] * invC;
    const float var  = s2[0] * invC - mean * mean;
    const float rstd = rsqrtf(var + 1e-5f);
    float* q = out + (size_t)row * C;
    for (int i = threadIdx.x; i < C; i += 256) {
        float v = p[i];
        q[i] = (v - mean) * rstd * gamma[i] + beta[i];
    }
}

// ---------------------------------------------------------------------------
// tf32 tensor-core GEMM (NT): C[M,N] = A[M,K] * B[N,K]^T (+ bias[N])
// BM=128, BN=64, BK=32. 256 thr = 8 warps (4x2), warp tile 32x32.
// Operands rounded to tf32 (cvt.rna) at smem staging.
// Smem strides 36 -> all fragment LDS are bank-conflict-free.
// ---------------------------------------------------------------------------
__global__ __launch_bounds__(256) void gemm_tf32(
    const float* __restrict__ A, const float* __restrict__ Bm,
    const float* __restrict__ bias, float* __restrict__ C,
    int M, int N, int K)
{
    __shared__ float As[128][36];
    __shared__ float Bs[64][36];

    const int tid  = threadIdx.x;
    const int warp = tid >> 5, lane = tid & 31;
    const int wm = warp & 3, wn = warp >> 2;
    const int gr = lane >> 2, tg = lane & 3;
    const int rowBase = blockIdx.y * 128;
    const int colBase = blockIdx.x * 64;

    float acc[2][4][4];
    #pragma unroll
    for (int i = 0; i < 2; i++)
        #pragma unroll
        for (int j = 0; j < 4; j++)
            #pragma unroll
            for (int t = 0; t < 4; t++) acc[i][j][t] = 0.f;

    // staging assignment
    const int arow = tid >> 1;         // 0..127, 16 elems each
    const int acol = (tid & 1) * 16;
    const int brow = tid >> 2;         // 0..63, 8 elems each
    const int bcol = (tid & 3) * 8;
    const float* Aptr = A  + (size_t)(rowBase + arow) * K + acol;
    const float* Bptr = Bm + (size_t)(colBase + brow) * K + bcol;

    float4 af[4], bf[2];
    #pragma unroll
    for (int i = 0; i < 4; i++) af[i] = *reinterpret_cast<const float4*>(Aptr + i * 4);
    #pragma unroll
    for (int i = 0; i < 2; i++) bf[i] = *reinterpret_cast<const float4*>(Bptr + i * 4);

    for (int k0 = 0; k0 < K; k0 += 32) {
        #pragma unroll
        for (int i = 0; i < 4; i++) {
            As[arow][acol + i * 4 + 0] = to_tf32(af[i].x);
            As[arow][acol + i * 4 + 1] = to_tf32(af[i].y);
            As[arow][acol + i * 4 + 2] = to_tf32(af[i].z);
            As[arow][acol + i * 4 + 3] = to_tf32(af[i].w);
        }
        #pragma unroll
        for (int i = 0; i < 2; i++) {
            Bs[brow][bcol + i * 4 + 0] = to_tf32(bf[i].x);
            Bs[brow][bcol + i * 4 + 1] = to_tf32(bf[i].y);
            Bs[brow][bcol + i * 4 + 2] = to_tf32(bf[i].z);
            Bs[brow][bcol + i * 4 + 3] = to_tf32(bf[i].w);
        }
        __syncthreads();

        // prefetch next tile into registers (overlaps with MMA)
        if (k0 + 32 < K) {
            #pragma unroll
            for (int i = 0; i < 4; i++)
                af[i] = *reinterpret_cast<const float4*>(Aptr + k0 + 32 + i * 4);
            #pragma unroll
            for (int i = 0; i < 2; i++)
                bf[i] = *reinterpret_cast<const float4*>(Bptr + k0 + 32 + i * 4);
        }

        #pragma unroll
        for (int ks = 0; ks < 4; ks++) {
            uint32_t a[2][4];
            #pragma unroll
            for (int mt = 0; mt < 2; mt++) {
                const int r0 = wm * 32 + mt * 16 + gr;
                a[mt][0] = __float_as_uint(As[r0    ][ks * 8 + tg]);
                a[mt][1] = __float_as_uint(As[r0 + 8][ks * 8 + tg]);
                a[mt][2] = __float_as_uint(As[r0    ][ks * 8 + tg + 4]);
                a[mt][3] = __float_as_uint(As[r0 + 8][ks * 8 + tg + 4]);
            }
            #pragma unroll
            for (int nt = 0; nt < 4; nt++) {
                const int c0 = wn * 32 + nt * 8 + gr;
                const uint32_t b0 = __float_as_uint(Bs[c0][ks * 8 + tg]);
                const uint32_t b1 = __float_as_uint(Bs[c0][ks * 8 + tg + 4]);
                mma_tf32(acc[0][nt], a[0][0], a[0][1], a[0][2], a[0][3], b0, b1);
                mma_tf32(acc[1][nt], a[1][0], a[1][1], a[1][2], a[1][3], b0, b1);
            }
        }
        __syncthreads();
    }

    #pragma unroll
    for (int mt = 0; mt < 2; mt++) {
        const int row0 = rowBase + wm * 32 + mt * 16 + gr;
        #pragma unroll
        for (int nt = 0; nt < 4; nt++) {
            const int col = colBase + wn * 32 + nt * 8 + 2 * tg;
            float bx = 0.f, by = 0.f;
            if (bias) { bx = bias[col]; by = bias[col + 1]; }
            *reinterpret_cast<float2*>(&C[(size_t)row0 * N + col]) =
                make_float2(acc[mt][nt][0] + bx, acc[mt][nt][1] + by);
            *reinterpret_cast<float2*>(&C[(size_t)(row0 + 8) * N + col]) =
                make_float2(acc[mt][nt][2] + bx, acc[mt][nt][3] + by);
        }
    }
}

// ---------------------------------------------------------------------------
// Flash attention with tf32 MMA. grid = (N/64, B*HEADS), 256 thr (8 warps).
// QK^T via mma (warp: rows wm*16+16, keys wn*32+32).
// Softmax on smem S, exp spread over all 256 threads, P rounded to tf32.
// PV via mma (warp: rows wm*16+16, dims wn*16+16). Residual fused in epilogue.
// ---------------------------------------------------------------------------
__global__ __launch_bounds__(256) void attn_mma(
    const float* __restrict__ Q, const float* __restrict__ K,
    const float* __restrict__ V, const float* __restrict__ H,
    float* __restrict__ Out)
{
    __shared__ float Qs[64][36];
    __shared__ float Ks[64][36];
    __shared__ float Vs[64][40];
    __shared__ float Ss[64][68];
    __shared__ float red[4][64];
    __shared__ float m_s[64], l_s[64], a_s[64];

    const int tid  = threadIdx.x;
    const int warp = tid >> 5, lane = tid & 31;
    const int wm = warp & 3, wn = warp >> 2;
    const int gr = lane >> 2, tg = lane & 3;
    const int bh = blockIdx.y;
    const int b  = bh / HEADS_;
    const int h  = bh % HEADS_;
    const int n0 = blockIdx.x * 64;
    const size_t headoff = (size_t)(b * N_) * CR_ + h * HD_;
    const float scale = 0.17677669529663687f;  // 1/sqrt(32)

    // stage Q tile (pre-scaled, tf32-rounded)
    {
        const int r  = tid >> 2;
        const int c0 = (tid & 3) * 8;
        const float* qp = Q + headoff + (size_t)(n0 + r) * CR_ + c0;
        float4 v0 = *reinterpret_cast<const float4*>(qp);
        float4 v1 = *reinterpret_cast<const float4*>(qp + 4);
        Qs[r][c0 + 0] = to_tf32(v0.x * scale);
        Qs[r][c0 + 1] = to_tf32(v0.y * scale);
        Qs[r][c0 + 2] = to_tf32(v0.z * scale);
        Qs[r][c0 + 3] = to_tf32(v0.w * scale);
        Qs[r][c0 + 4] = to_tf32(v1.x * scale);
        Qs[r][c0 + 5] = to_tf32(v1.y * scale);
        Qs[r][c0 + 6] = to_tf32(v1.z * scale);
        Qs[r][c0 + 7] = to_tf32(v1.w * scale);
    }
    if (tid < 64) { m_s[tid] = -INFINITY; l_s[tid] = 0.f; }
    __syncthreads();

    // Q A-fragments, held in regs for the whole kernel
    uint32_t qa[4][4];
    #pragma unroll
    for (int ks = 0; ks < 4; ks++) {
        const int r0 = wm * 16 + gr;
        qa[ks][0] = __float_as_uint(Qs[r0    ][ks * 8 + tg]);
        qa[ks][1] = __float_as_uint(Qs[r0 + 8][ks * 8 + tg]);
        qa[ks][2] = __float_as_uint(Qs[r0    ][ks * 8 + tg + 4]);
        qa[ks][3] = __float_as_uint(Qs[r0 + 8][ks * 8 + tg + 4]);
    }

    float oacc[2][4];
    #pragma unroll
    for (int nt = 0; nt < 2; nt++)
        #pragma unroll
        for (int t = 0; t < 4; t++) oacc[nt][t] = 0.f;

    const int lr = tid >> 2, lc = (tid & 3) * 8;  // K/V staging
    const int sr = tid & 63, sg = tid >> 6;       // softmax mapping

    for (int kt = 0; kt < N_ / 64; kt++) {
        __syncthreads();  // previous tile's Ss/Vs reads done
        {
            const size_t off = headoff + (size_t)(kt * 64 + lr) * CR_ + lc;
            float4 k0v = *reinterpret_cast<const float4*>(K + off);
            float4 k1v = *reinterpret_cast<const float4*>(K + off + 4);
            float4 v0v = *reinterpret_cast<const float4*>(V + off);
            float4 v1v = *reinterpret_cast<const float4*>(V + off + 4);
            Ks[lr][lc + 0] = to_tf32(k0v.x); Ks[lr][lc + 1] = to_tf32(k0v.y);
            Ks[lr][lc + 2] = to_tf32(k0v.z); Ks[lr][lc + 3] = to_tf32(k0v.w);
            Ks[lr][lc + 4] = to_tf32(k1v.x); Ks[lr][lc + 5] = to_tf32(k1v.y);
            Ks[lr][lc + 6] = to_tf32(k1v.z); Ks[lr][lc + 7] = to_tf32(k1v.w);
            Vs[lr][lc + 0] = to_tf32(v0v.x); Vs[lr][lc + 1] = to_tf32(v0v.y);
            Vs[lr][lc + 2] = to_tf32(v0v.z); Vs[lr][lc + 3] = to_tf32(v0v.w);
            Vs[lr][lc + 4] = to_tf32(v1v.x); Vs[lr][lc + 5] = to_tf32(v1v.y);
            Vs[lr][lc + 6] = to_tf32(v1v.z); Vs[lr][lc + 7] = to_tf32(v1v.w);
        }
        __syncthreads();

        // S = (Q*scale) K^T
        float sacc[4][4];
        #pragma unroll
        for (int nt = 0; nt < 4; nt++)
            #pragma unroll
            for (int t = 0; t < 4; t++) sacc[nt][t] = 0.f;
        #pragma unroll
        for (int ks = 0; ks < 4; ks++) {
            #pragma unroll
            for (int nt = 0; nt < 4; nt++) {
                const int kc = wn * 32 + nt * 8 + gr;
                const uint32_t b0 = __float_as_uint(Ks[kc][ks * 8 + tg]);
                const uint32_t b1 = __float_as_uint(Ks[kc][ks * 8 + tg + 4]);
                mma_tf32(sacc[nt], qa[ks][0], qa[ks][1], qa[ks][2], qa[ks][3], b0, b1);
            }
        }
        #pragma unroll
        for (int nt = 0; nt < 4; nt++) {
            const int r0 = wm * 16 + gr, c = wn * 32 + nt * 8 + 2 * tg;
            *reinterpret_cast<float2*>(&Ss[r0    ][c]) = make_float2(sacc[nt][0], sacc[nt][1]);
            *reinterpret_cast<float2*>(&Ss[r0 + 8][c]) = make_float2(sacc[nt][2], sacc[nt][3]);
        }
        __syncthreads();

        // online softmax: thread (sr, sg) owns cols sg*16..+15 of row sr
        float sv[16];
        float pmax = -INFINITY;
        #pragma unroll
        for (int i = 0; i < 16; i++) {
            sv[i] = Ss[sr][sg * 16 + i];
            pmax = fmaxf(pmax, sv[i]);
        }
        red[sg][sr] = pmax;
        __syncthreads();
        const float m_old = m_s[sr];
        const float m_new = fmaxf(m_old,
            fmaxf(fmaxf(red[0][sr], red[1][sr]), fmaxf(red[2][sr], red[3][sr])));
        float psum = 0.f;
        #pragma unroll
        for (int i = 0; i < 16; i++) {
            float p = __expf(sv[i] - m_new);
            psum += p;
            Ss[sr][sg * 16 + i] = to_tf32(p);
        }
        __syncthreads();  // all reads of red(max) done
        red[sg][sr] = psum;
        __syncthreads();
        if (sg == 0) {
            const float alpha = __expf(m_old - m_new);
            a_s[sr] = alpha;
            m_s[sr] = m_new;
            l_s[sr] = l_s[sr] * alpha +
                      red[0][sr] + red[1][sr] + red[2][sr] + red[3][sr];
        }
        __syncthreads();

        // O = O*alpha + P @ V
        const float al0 = a_s[wm * 16 + gr];
        const float al1 = a_s[wm * 16 + gr + 8];
        #pragma unroll
        for (int nt = 0; nt < 2; nt++) {
            oacc[nt][0] *= al0; oacc[nt][1] *= al0;
            oacc[nt][2] *= al1; oacc[nt][3] *= al1;
        }
        #pragma unroll
        for (int ks = 0; ks < 8; ks++) {
            const int r0 = wm * 16 + gr;
            const uint32_t a0 = __float_as_uint(Ss[r0    ][ks * 8 + tg]);
            const uint32_t a1 = __float_as_uint(Ss[r0 + 8][ks * 8 + tg]);
            const uint32_t a2 = __float_as_uint(Ss[r0    ][ks * 8 + tg + 4]);
            const uint32_t a3 = __float_as_uint(Ss[r0 + 8][ks * 8 + tg + 4]);
            #pragma unroll
            for (int nt = 0; nt < 2; nt++) {
                const int vc = wn * 16 + nt * 8 + gr;
                const uint32_t b0 = __float_as_uint(Vs[ks * 8 + tg    ][vc]);
                const uint32_t b1 = __float_as_uint(Vs[ks * 8 + tg + 4][vc]);
                mma_tf32(oacc[nt], a0, a1, a2, a3, b0, b1);
            }
        }
    }

    // epilogue: out = h + O/l
    const int r0 = wm * 16 + gr;
    const float li0 = 1.f / l_s[r0];
    const float li1 = 1.f / l_s[r0 + 8];
    #pragma unroll
    for (int nt = 0; nt < 2; nt++) {
        const int col = h * HD_ + wn * 16 + nt * 8 + 2 * tg;
        const size_t i0 = (size_t)(b * N_ + n0 + r0) * CR_ + col;
        const size_t i1 = (size_t)(b * N_ + n0 + r0 + 8) * CR_ + col;
        float2 h0 = *reinterpret_cast<const float2*>(H + i0);
        float2 h1 = *reinterpret_cast<const float2*>(H + i1);
        *reinterpret_cast<float2*>(Out + i0) =
            make_float2(h0.x + oacc[nt][0] * li0, h0.y + oacc[nt][1] * li0);
        *reinterpret_cast<float2*>(Out + i1) =
            make_float2(h1.x + oacc[nt][2] * li1, h1.y + oacc[nt][3] * li1);
    }
}

// ---------------------------------------------------------------------------
// Launch
// ---------------------------------------------------------------------------
extern "C" void kernel_launch(void* const* d_in, const int* in_sizes, int n_in,
                              void* d_out, int out_size)
{
    (void)in_sizes; (void)n_in; (void)out_size;
    const float* x      = (const float*)d_in[0];
    const float* ln0_g  = (const float*)d_in[1];
    const float* ln0_b  = (const float*)d_in[2];
    const float* w_proj = (const float*)d_in[3];
    const float* b_proj = (const float*)d_in[4];
    const float* ln1_g  = (const float*)d_in[5];
    const float* ln1_b  = (const float*)d_in[6];
    const float* wq     = (const float*)d_in[7];
    const float* wk     = (const float*)d_in[8];
    const float* wv     = (const float*)d_in[9];
    float* out = (float*)d_out;

    float *xn, *h, *y, *q, *k, *v;
    cudaGetSymbolAddress((void**)&xn, g_xn);
    cudaGetSymbolAddress((void**)&h,  g_h);
    cudaGetSymbolAddress((void**)&y,  g_y);
    cudaGetSymbolAddress((void**)&q,  g_q);
    cudaGetSymbolAddress((void**)&k,  g_k);
    cudaGetSymbolAddress((void**)&v,  g_v);

    // 1) xn = LN0(x)
    ln_kernel<<<ROWS_, 256>>>(x, ln0_g, ln0_b, xn, DIM_);

    // 2) h = xn @ w_proj^T + b_proj   [8192, 384]
    gemm_tf32<<<dim3(CR_ / 64, ROWS_ / 128), 256>>>(
        xn, w_proj, b_proj, h, ROWS_, CR_, DIM_);

    // 3) y = LN1(h)
    ln_kernel<<<ROWS_, 256>>>(h, ln1_g, ln1_b, y, CR_);

    // 4) q/k/v = y @ w^T
    gemm_tf32<<<dim3(CR_ / 64, ROWS_ / 128), 256>>>(
        y, wq, nullptr, q, ROWS_, CR_, CR_);
    gemm_tf32<<<dim3(CR_ / 64, ROWS_ / 128), 256>>>(
        y, wk, nullptr, k, ROWS_, CR_, CR_);
    gemm_tf32<<<dim3(CR_ / 64, ROWS_ / 128), 256>>>(
        y, wv, nullptr, v, ROWS_, CR_, CR_);

    // 5) out = h + attention(y)
    attn_mma<<<dim3(N_ / 64, B_ * HEADS_), 256>>>(q, k, v, h, out);
}

// round 6
// speedup vs baseline: 3.7232x; 1.6715x over previous
#include <cuda_runtime.h>
#include <math.h>
#include <stdint.h>

// Problem constants
#define B_     8
#define N_     1024
#define DIM_   768
#define CR_    384
#define HEADS_ 12
#define HD_    32
#define ROWS_  (B_ * N_)   // 8192

// Scratch (device globals; no allocations allowed)
__device__ float g_xn[ROWS_ * DIM_];
__device__ float g_h [ROWS_ * CR_];
__device__ float g_y [ROWS_ * CR_];
__device__ float g_q [ROWS_ * CR_];
__device__ float g_k [ROWS_ * CR_];
__device__ float g_v [ROWS_ * CR_];

// ---------------------------------------------------------------------------
// PTX helpers
// ---------------------------------------------------------------------------
__device__ __forceinline__ uint32_t smem_u32(const void* p) {
    return (uint32_t)__cvta_generic_to_shared(p);
}
__device__ __forceinline__ void ldsm_x4(uint32_t a, uint32_t& r0, uint32_t& r1,
                                        uint32_t& r2, uint32_t& r3) {
    asm volatile("ldmatrix.sync.aligned.m8n8.x4.shared.b16 {%0,%1,%2,%3}, [%4];"
                 : "=r"(r0), "=r"(r1), "=r"(r2), "=r"(r3) : "r"(a));
}
#define CP16(dst, src) \
    asm volatile("cp.async.ca.shared.global [%0], [%1], 16;" :: "r"(dst), "l"(src))
#define CP_COMMIT() asm volatile("cp.async.commit_group;")
#define CP_WAIT(n)  asm volatile("cp.async.wait_group %0;" :: "n"(n))

__device__ __forceinline__ void mma_tf32(float* c, const uint32_t* a,
                                         uint32_t b0, uint32_t b1) {
    asm volatile(
        "mma.sync.aligned.m16n8k8.row.col.f32.tf32.tf32.f32 "
        "{%0,%1,%2,%3}, {%4,%5,%6,%7}, {%8,%9}, {%0,%1,%2,%3};"
        : "+f"(c[0]), "+f"(c[1]), "+f"(c[2]), "+f"(c[3])
        : "r"(a[0]), "r"(a[1]), "r"(a[2]), "r"(a[3]), "r"(b0), "r"(b1));
}

// ---------------------------------------------------------------------------
// Row-wise LayerNorm: one block per row, C/4 threads, float4 path.
// ---------------------------------------------------------------------------
__global__ void ln_kernel(const float* __restrict__ in,
                          const float* __restrict__ gamma,
                          const float* __restrict__ beta,
                          float* __restrict__ out, int C)
{
    const int row = blockIdx.x;
    const int tid = threadIdx.x;
    const float4 v = reinterpret_cast<const float4*>(in + (size_t)row * C)[tid];
    float sum = v.x + v.y + v.z + v.w;
    float sq  = v.x * v.x + v.y * v.y + v.z * v.z + v.w * v.w;

    __shared__ float s1[8], s2[8];
    #pragma unroll
    for (int o = 16; o; o >>= 1) {
        sum += __shfl_xor_sync(0xffffffffu, sum, o);
        sq  += __shfl_xor_sync(0xffffffffu, sq,  o);
    }
    const int w = tid >> 5, l = tid & 31;
    const int nw = blockDim.x >> 5;
    if (l == 0) { s1[w] = sum; s2[w] = sq; }
    __syncthreads();
    if (tid == 0) {
        float a = 0.f, c2 = 0.f;
        for (int i = 0; i < nw; i++) { a += s1[i]; c2 += s2[i]; }
        s1[0] = a; s2[0] = c2;
    }
    __syncthreads();
    const float invC = 1.0f / (float)C;
    const float mean = s1[0] * invC;
    const float var  = s2[0] * invC - mean * mean;
    const float rstd = rsqrtf(var + 1e-5f);

    const float4 gv = reinterpret_cast<const float4*>(gamma)[tid];
    const float4 bv = reinterpret_cast<const float4*>(beta)[tid];
    float4 o;
    o.x = (v.x - mean) * rstd * gv.x + bv.x;
    o.y = (v.y - mean) * rstd * gv.y + bv.y;
    o.z = (v.z - mean) * rstd * gv.z + bv.z;
    o.w = (v.w - mean) * rstd * gv.w + bv.w;
    reinterpret_cast<float4*>(out + (size_t)row * C)[tid] = o;
}

// ---------------------------------------------------------------------------
// tf32 GEMM (NT): C[M,384] = A[M,K] * W[384,K]^T (+bias). N fixed to 384.
// BM=128, BN=64, BK=32; 256 thr = 8 warps (4 M x 2 N), warp tile 32x32.
// cp.async double-buffered smem; ldmatrix fragment loads.
// grid.z selects (W,C) among up to 3 pairs (QKV fusion).
// ---------------------------------------------------------------------------
#define GN_ 384
__global__ __launch_bounds__(256) void gemm_tf32(
    const float* __restrict__ A,
    const float* __restrict__ W0, const float* __restrict__ W1,
    const float* __restrict__ W2, const float* __restrict__ bias,
    float* __restrict__ O0, float* __restrict__ O1, float* __restrict__ O2,
    int K)
{
    extern __shared__ float sm[];
    float* As = sm;                      // [2][128][36]
    float* Bs = sm + 2 * 128 * 36;       // [2][64][36]
    const int ABUF = 128 * 36, BBUF = 64 * 36;

    const float* Bm = W0; float* C = O0;
    if (blockIdx.z == 1) { Bm = W1; C = O1; }
    if (blockIdx.z == 2) { Bm = W2; C = O2; }

    const int tid = threadIdx.x, lane = tid & 31, warp = tid >> 5;
    const int wm = warp & 3, wn = warp >> 2;
    const int gr = lane >> 2, tg = lane & 3;
    const int rowBase = blockIdx.y * 128, colBase = blockIdx.x * 64;

    const uint32_t as0 = smem_u32(As), bs0 = smem_u32(Bs);

    // fragment LDSM byte addresses (buffer 0)
    uint32_t a_addr[2], b_addr[2];
    {
        const int r = lane & 15, c = (lane >> 4) << 2;
        a_addr[0] = as0 + (uint32_t)(((wm * 32 + r) * 36 + c) * 4);
        a_addr[1] = a_addr[0] + 16 * 36 * 4;
        const int rb = ((lane >> 3) & 1) * 8 + (lane & 7);
        b_addr[0] = bs0 + (uint32_t)(((wn * 32 + rb) * 36 + c) * 4);
        b_addr[1] = b_addr[0] + 16 * 36 * 4;
    }

    auto stage = [&](int t, int buf) {
        const int k0 = t << 5;
        #pragma unroll
        for (int i = 0; i < 4; i++) {
            const int id = tid + i * 256;
            const int r = id >> 3, ch = (id & 7) << 2;
            CP16(as0 + (uint32_t)((buf * ABUF + r * 36 + ch) * 4),
                 A + (size_t)(rowBase + r) * K + k0 + ch);
        }
        #pragma unroll
        for (int i = 0; i < 2; i++) {
            const int id = tid + i * 256;
            const int r = id >> 3, ch = (id & 7) << 2;
            CP16(bs0 + (uint32_t)((buf * BBUF + r * 36 + ch) * 4),
                 Bm + (size_t)(colBase + r) * K + k0 + ch);
        }
    };

    float acc[2][4][4] = {};

    const int T = K >> 5;
    stage(0, 0);
    CP_COMMIT();

    for (int t = 0; t < T; t++) {
        __syncthreads();
        if (t + 1 < T) { stage(t + 1, (t + 1) & 1); CP_COMMIT(); CP_WAIT(1); }
        else           { CP_WAIT(0); }
        __syncthreads();

        const uint32_t aoff = (uint32_t)((t & 1) * ABUF * 4);
        const uint32_t boff = (uint32_t)((t & 1) * BBUF * 4);
        #pragma unroll
        for (int ks = 0; ks < 4; ks++) {
            uint32_t a[2][4], bb[2][4];
            ldsm_x4(a_addr[0] + aoff + ks * 32, a[0][0], a[0][1], a[0][2], a[0][3]);
            ldsm_x4(a_addr[1] + aoff + ks * 32, a[1][0], a[1][1], a[1][2], a[1][3]);
            ldsm_x4(b_addr[0] + boff + ks * 32, bb[0][0], bb[0][1], bb[0][2], bb[0][3]);
            ldsm_x4(b_addr[1] + boff + ks * 32, bb[1][0], bb[1][1], bb[1][2], bb[1][3]);
            #pragma unroll
            for (int p = 0; p < 2; p++)
                #pragma unroll
                for (int q = 0; q < 2; q++) {
                    const int nt = p * 2 + q;
                    mma_tf32(acc[0][nt], a[0], bb[p][q], bb[p][q + 2]);
                    mma_tf32(acc[1][nt], a[1], bb[p][q], bb[p][q + 2]);
                }
        }
    }

    #pragma unroll
    for (int mt = 0; mt < 2; mt++) {
        const int row0 = rowBase + wm * 32 + mt * 16 + gr;
        #pragma unroll
        for (int nt = 0; nt < 4; nt++) {
            const int col = colBase + wn * 32 + nt * 8 + 2 * tg;
            float bx = 0.f, by = 0.f;
            if (bias) { bx = bias[col]; by = bias[col + 1]; }
            *reinterpret_cast<float2*>(&C[(size_t)row0 * GN_ + col]) =
                make_float2(acc[mt][nt][0] + bx, acc[mt][nt][1] + by);
            *reinterpret_cast<float2*>(&C[(size_t)(row0 + 8) * GN_ + col]) =
                make_float2(acc[mt][nt][2] + bx, acc[mt][nt][3] + by);
        }
    }
}

// ---------------------------------------------------------------------------
// Warp-synchronous flash attention, tf32 MMA.
// grid = (N/64, B*HEADS), 128 thr = 4 warps; each warp: 16 Q rows x 64 keys.
// S + softmax in registers (quad shuffles); P via warp-private smem + ldmatrix.
// K/V double-buffered cp.async. Residual fused in epilogue.
// ---------------------------------------------------------------------------
__global__ __launch_bounds__(128) void attn_mma(
    const float* __restrict__ Q, const float* __restrict__ K,
    const float* __restrict__ V, const float* __restrict__ H,
    float* __restrict__ Out)
{
    extern __shared__ float sm[];
    float* Ks = sm;                 // [2][64][36]  = 4608 floats
    float* Vs = sm + 4608;          // [2][64][40]  = 5120 floats
    float* Ps = sm + 9728;          // [4][16][68]  = 4352 floats (Q staged here first)
    const int KSB = 64 * 36, VSB = 64 * 40;

    const int tid = threadIdx.x, lane = tid & 31, wm = tid >> 5;
    const int gr = lane >> 2, tg = lane & 3;
    const int b = blockIdx.y / HEADS_, h = blockIdx.y % HEADS_;
    const int n0 = blockIdx.x * 64;
    const size_t headoff = (size_t)(b * N_) * CR_ + h * HD_;
    const float C2 = 0.17677669529663687f * 1.4426950408889634f; // scale*log2(e)

    const uint32_t ks0 = smem_u32(Ks), ps0 = smem_u32(Ps), vs0 = smem_u32(Vs);

    auto stageKV = [&](int t, int buf) {
        const int r0 = t * 64;
        #pragma unroll
        for (int i = 0; i < 4; i++) {
            const int id = tid + i * 128;
            const int r = id >> 3, ch = (id & 7) << 2;
            CP16(ks0 + (uint32_t)((buf * KSB + r * 36 + ch) * 4),
                 K + headoff + (size_t)(r0 + r) * CR_ + ch);
        }
        #pragma unroll
        for (int i = 0; i < 4; i++) {
            const int id = tid + i * 128;
            const int r = id >> 3, ch = (id & 7) << 2;
            CP16(vs0 + (uint32_t)((buf * VSB + r * 40 + ch) * 4),
                 V + headoff + (size_t)(r0 + r) * CR_ + ch);
        }
    };

    // prologue: stage Q (into Ps region, stride 36) + K/V tile 0
    #pragma unroll
    for (int i = 0; i < 4; i++) {
        const int id = tid + i * 128;
        const int r = id >> 3, ch = (id & 7) << 2;
        CP16(ps0 + (uint32_t)((r * 36 + ch) * 4),
             Q + headoff + (size_t)(n0 + r) * CR_ + ch);
    }
    stageKV(0, 0);
    CP_COMMIT();
    CP_WAIT(0);
    __syncthreads();

    // Q fragments (held in regs for whole kernel)
    uint32_t qa[4][4];
    {
        const uint32_t qb = ps0 +
            (uint32_t)((((wm * 16 + (lane & 15)) * 36) + ((lane >> 4) << 2)) * 4);
        #pragma unroll
        for (int ks = 0; ks < 4; ks++)
            ldsm_x4(qb + ks * 32, qa[ks][0], qa[ks][1], qa[ks][2], qa[ks][3]);
    }
    __syncthreads();  // all warps read Q before Ps is reused for P

    // fragment addresses
    uint32_t kb_addr[4];
    {
        const int rb = ((lane >> 3) & 1) * 8 + (lane & 7);
        const int c = (lane >> 4) << 2;
        #pragma unroll
        for (int p = 0; p < 4; p++)
            kb_addr[p] = ks0 + (uint32_t)(((p * 16 + rb) * 36 + c) * 4);
    }
    const uint32_t pa_addr = ps0 +
        (uint32_t)((((wm * 16 + (lane & 15)) * 68) + ((lane >> 4) << 2)) * 4);

    float m0 = -INFINITY, m1 = -INFINITY, l0 = 0.f, l1 = 0.f;
    float oacc[4][4] = {};

    for (int kt = 0; kt < N_ / 64; kt++) {
        __syncthreads();
        if (kt + 1 < N_ / 64) { stageKV(kt + 1, (kt + 1) & 1); CP_COMMIT(); CP_WAIT(1); }
        else                  { CP_WAIT(0); }
        __syncthreads();

        const uint32_t kboff = (uint32_t)((kt & 1) * KSB * 4);
        const float* Vcur = Vs + (kt & 1) * VSB;

        // S = Q K^T  (16 LDSM + 32 MMA)
        float sc[8][4] = {};
        #pragma unroll
        for (int ks = 0; ks < 4; ks++)
            #pragma unroll
            for (int p = 0; p < 4; p++) {
                uint32_t r0, r1, r2, r3;
                ldsm_x4(kb_addr[p] + kboff + ks * 32, r0, r1, r2, r3);
                mma_tf32(sc[2 * p],     qa[ks], r0, r2);
                mma_tf32(sc[2 * p + 1], qa[ks], r1, r3);
            }

        // online softmax in registers
        float mx0 = sc[0][0], mx1 = sc[0][2];
        #pragma unroll
        for (int nt = 0; nt < 8; nt++) {
            mx0 = fmaxf(mx0, fmaxf(sc[nt][0], sc[nt][1]));
            mx1 = fmaxf(mx1, fmaxf(sc[nt][2], sc[nt][3]));
        }
        mx0 = fmaxf(mx0, __shfl_xor_sync(0xffffffffu, mx0, 1));
        mx0 = fmaxf(mx0, __shfl_xor_sync(0xffffffffu, mx0, 2));
        mx1 = fmaxf(mx1, __shfl_xor_sync(0xffffffffu, mx1, 1));
        mx1 = fmaxf(mx1, __shfl_xor_sync(0xffffffffu, mx1, 2));
        const float mn0 = fmaxf(m0, mx0), mn1 = fmaxf(m1, mx1);
        const float al0 = exp2f((m0 - mn0) * C2);
        const float al1 = exp2f((m1 - mn1) * C2);
        m0 = mn0; m1 = mn1;
        const float nm0 = mn0 * C2, nm1 = mn1 * C2;
        float s0 = 0.f, s1 = 0.f;
        #pragma unroll
        for (int nt = 0; nt < 8; nt++) {
            sc[nt][0] = exp2f(fmaf(sc[nt][0], C2, -nm0)); s0 += sc[nt][0];
            sc[nt][1] = exp2f(fmaf(sc[nt][1], C2, -nm0)); s0 += sc[nt][1];
            sc[nt][2] = exp2f(fmaf(sc[nt][2], C2, -nm1)); s1 += sc[nt][2];
            sc[nt][3] = exp2f(fmaf(sc[nt][3], C2, -nm1)); s1 += sc[nt][3];
        }
        s0 += __shfl_xor_sync(0xffffffffu, s0, 1);
        s0 += __shfl_xor_sync(0xffffffffu, s0, 2);
        s1 += __shfl_xor_sync(0xffffffffu, s1, 1);
        s1 += __shfl_xor_sync(0xffffffffu, s1, 2);
        l0 = l0 * al0 + s0;
        l1 = l1 * al1 + s1;
        #pragma unroll
        for (int nt = 0; nt < 4; nt++) {
            oacc[nt][0] *= al0; oacc[nt][1] *= al0;
            oacc[nt][2] *= al1; oacc[nt][3] *= al1;
        }

        // P -> warp-private smem, back as A-fragments via ldmatrix
        __syncwarp();
        #pragma unroll
        for (int nt = 0; nt < 8; nt++) {
            *reinterpret_cast<float2*>(&Ps[(wm * 16 + gr) * 68 + nt * 8 + 2 * tg]) =
                make_float2(sc[nt][0], sc[nt][1]);
            *reinterpret_cast<float2*>(&Ps[(wm * 16 + gr + 8) * 68 + nt * 8 + 2 * tg]) =
                make_float2(sc[nt][2], sc[nt][3]);
        }
        __syncwarp();

        // O += P @ V  (8 LDSM + 64 LDS + 32 MMA)
        #pragma unroll
        for (int ks2 = 0; ks2 < 8; ks2++) {
            uint32_t pa[4];
            ldsm_x4(pa_addr + ks2 * 32, pa[0], pa[1], pa[2], pa[3]);
            #pragma unroll
            for (int nt = 0; nt < 4; nt++) {
                const uint32_t b0 =
                    __float_as_uint(Vcur[(ks2 * 8 + tg) * 40 + nt * 8 + gr]);
                const uint32_t b1 =
                    __float_as_uint(Vcur[(ks2 * 8 + tg + 4) * 40 + nt * 8 + gr]);
                mma_tf32(oacc[nt], pa, b0, b1);
            }
        }
    }

    // epilogue: out = h + O/l
    const float i0 = 1.f / l0, i1 = 1.f / l1;
    const int r0 = n0 + wm * 16 + gr;
    #pragma unroll
    for (int nt = 0; nt < 4; nt++) {
        const int col = h * HD_ + nt * 8 + 2 * tg;
        const size_t idx0 = (size_t)(b * N_ + r0) * CR_ + col;
        const size_t idx1 = (size_t)(b * N_ + r0 + 8) * CR_ + col;
        const float2 h0 = *reinterpret_cast<const float2*>(H + idx0);
        const float2 h1 = *reinterpret_cast<const float2*>(H + idx1);
        *reinterpret_cast<float2*>(Out + idx0) =
            make_float2(h0.x + oacc[nt][0] * i0, h0.y + oacc[nt][1] * i0);
        *reinterpret_cast<float2*>(Out + idx1) =
            make_float2(h1.x + oacc[nt][2] * i1, h1.y + oacc[nt][3] * i1);
    }
}

// ---------------------------------------------------------------------------
// Launch
// ---------------------------------------------------------------------------
extern "C" void kernel_launch(void* const* d_in, const int* in_sizes, int n_in,
                              void* d_out, int out_size)
{
    (void)in_sizes; (void)n_in; (void)out_size;
    const float* x      = (const float*)d_in[0];
    const float* ln0_g  = (const float*)d_in[1];
    const float* ln0_b  = (const float*)d_in[2];
    const float* w_proj = (const float*)d_in[3];
    const float* b_proj = (const float*)d_in[4];
    const float* ln1_g  = (const float*)d_in[5];
    const float* ln1_b  = (const float*)d_in[6];
    const float* wq     = (const float*)d_in[7];
    const float* wk     = (const float*)d_in[8];
    const float* wv     = (const float*)d_in[9];
    float* out = (float*)d_out;

    float *xn, *h, *y, *q, *k, *v;
    cudaGetSymbolAddress((void**)&xn, g_xn);
    cudaGetSymbolAddress((void**)&h,  g_h);
    cudaGetSymbolAddress((void**)&y,  g_y);
    cudaGetSymbolAddress((void**)&q,  g_q);
    cudaGetSymbolAddress((void**)&k,  g_k);
    cudaGetSymbolAddress((void**)&v,  g_v);

    const int gemm_smem = (2 * 128 * 36 + 2 * 64 * 36) * 4;   // 55296 B
    const int attn_smem = (4608 + 5120 + 4352) * 4;           // 56320 B
    static bool attr_done = false;
    if (!attr_done) {
        cudaFuncSetAttribute(gemm_tf32,
            cudaFuncAttributeMaxDynamicSharedMemorySize, gemm_smem);
        cudaFuncSetAttribute(attn_mma,
            cudaFuncAttributeMaxDynamicSharedMemorySize, attn_smem);
        attr_done = true;
    }

    // 1) xn = LN0(x)
    ln_kernel<<<ROWS_, DIM_ / 4>>>(x, ln0_g, ln0_b, xn, DIM_);

    // 2) h = xn @ w_proj^T + b_proj
    gemm_tf32<<<dim3(CR_ / 64, ROWS_ / 128, 1), 256, gemm_smem>>>(
        xn, w_proj, nullptr, nullptr, b_proj, h, nullptr, nullptr, DIM_);

    // 3) y = LN1(h)
    ln_kernel<<<ROWS_, CR_ / 4>>>(h, ln1_g, ln1_b, y, CR_);

    // 4) q/k/v = y @ w^T   (fused, grid.z = 3)
    gemm_tf32<<<dim3(CR_ / 64, ROWS_ / 128, 3), 256, gemm_smem>>>(
        y, wq, wk, wv, nullptr, q, k, v, CR_);

    // 5) out = h + attention(y)
    attn_mma<<<dim3(N_ / 64, B_ * HEADS_), 128, attn_smem>>>(q, k, v, h, out);
}